// round 13
// baseline (speedup 1.0000x reference)
#include <cuda_runtime.h>
#include <cuda_bf16.h>
#include <cstdint>

// ---------------- fixed problem dimensions ----------------
#define BB    64
#define SS    200
#define TT    32
#define VV    50000
#define EE    128
#define CC    128
#define HH    100
#define OUTD  104
#define NTREE (BB*SS)          // 12800
#define G3    (3*HH)           // 300
#define GXOFF ((size_t)NTREE*G3)   // offset of bwd half in packed gx

// ---------------- device scratch (static, no allocs) ----------------
__device__ float g_emb_proj[(size_t)VV*CC];     // 25.6 MB
__device__ float g_tree_vec[(size_t)NTREE*CC];  // 6.5 MB
__device__ float g_gx[(size_t)NTREE*(2*G3)];    // 30.7 MB packed: [dir][b][t][300]
__device__ float g_pool[BB*2*HH];

// ---------------- f32x2 helpers (GRU) ----------------
__device__ __forceinline__ void fma2(unsigned long long& d,
                                     unsigned long long a,
                                     unsigned long long b) {
    asm("fma.rn.f32x2 %0, %1, %2, %0;" : "+l"(d) : "l"(a), "l"(b));
}
__device__ __forceinline__ float f2lo(unsigned long long v) { return __uint_as_float((unsigned int)v); }
__device__ __forceinline__ float f2hi(unsigned long long v) { return __uint_as_float((unsigned int)(v >> 32)); }
__device__ __forceinline__ unsigned long long d2u(double x) { return (unsigned long long)__double_as_longlong(x); }

__device__ __forceinline__ float fast_sigmoid(float x) {
    return __fdividef(1.f, 1.f + __expf(-x));
}
__device__ __forceinline__ float fast_tanh(float x) {
    float t = __expf(-2.f * x);
    return __fdividef(1.f - t, 1.f + t);
}

// ---------------- warp-MMA helpers (plain PTX, no sm_103a-only features) ----------------
__device__ __forceinline__ uint32_t smem_u32(const void* p) {
    uint32_t a;
    asm("{ .reg .u64 t; cvta.to.shared.u64 t, %1; cvt.u32.u64 %0, t; }" : "=r"(a) : "l"(p));
    return a;
}
__device__ __forceinline__ void ldsm4(uint32_t* r, uint32_t addr) {
    asm volatile("ldmatrix.sync.aligned.m8n8.x4.shared.b16 {%0,%1,%2,%3}, [%4];"
                 : "=r"(r[0]), "=r"(r[1]), "=r"(r[2]), "=r"(r[3]) : "r"(addr));
}
__device__ __forceinline__ void mma_bf16(float* c, const uint32_t* a, const uint32_t* b) {
    asm volatile("mma.sync.aligned.m16n8k16.row.col.f32.bf16.bf16.f32 "
                 "{%0,%1,%2,%3}, {%4,%5,%6,%7}, {%8,%9}, {%0,%1,%2,%3};"
                 : "+f"(c[0]), "+f"(c[1]), "+f"(c[2]), "+f"(c[3])
                 : "r"(a[0]), "r"(a[1]), "r"(a[2]), "r"(a[3]), "r"(b[0]), "r"(b[1]));
}
__device__ __forceinline__ uint32_t sw_addr(uint32_t base, int row, int chunk) {
    return base + row * 256 + (((uint32_t)chunk ^ ((uint32_t)row & 7u)) << 4);
}

// ============================================================================
// Tensor-core GEMM via mma.sync (bf16, fp32 acc), split-precision:
//   C = Ah*Bh + Al*Bh + Ah*Bl + bias     (error ~2^-17 relative)
// B rows come from Bm (rows < bsplit) or Bm2 (rows >= bsplit); bias likewise.
// pack_mode==1: remap output (r, c<600) -> g_gx [dir][b][t][300] layout.
// ============================================================================
#define MMA_SMEM_BYTES (131072 + 256)

__global__ __launch_bounds__(256, 1)
void mma_gemm_kernel(const float* __restrict__ A,
                     const float* __restrict__ Bm,
                     const float* __restrict__ Bm2,
                     const float* __restrict__ bias,
                     const float* __restrict__ bias2,
                     int bsplit,
                     float* __restrict__ Cmat,
                     int M, int Ncols, int ldC, int pack_mode) {
    extern __shared__ char raw_smem[];
    uint32_t raw_u = smem_u32(raw_smem);
    uint32_t padb  = ((raw_u + 255u) & ~255u) - raw_u;
    char* sm = raw_smem + padb;
    const uint32_t uAhi = raw_u + padb;
    const uint32_t uAlo = uAhi + 32768;
    const uint32_t uBhi = uAhi + 65536;
    const uint32_t uBlo = uAhi + 98304;
    char* sAhi = sm;
    char* sAlo = sm + 32768;
    char* sBhi = sm + 65536;
    char* sBlo = sm + 98304;

    __shared__ float sbias[128];

    const int tid  = threadIdx.x;
    const int wid  = tid >> 5;
    const int lane = tid & 31;

    const int rbase  = blockIdx.x * 128;
    const int cbase  = blockIdx.y * 128;
    const int aValid = min(128, M - rbase);
    const int bValid = min(128, Ncols - cbase);

    if (tid < 128) {
        int g = cbase + tid;
        float bv = 0.f;
        if (g < Ncols)
            bv = (g < bsplit) ? (bias ? bias[g] : 0.f)
                              : (bias2 ? bias2[g - bsplit] : 0.f);
        sbias[tid] = bv;
    }

    if (aValid < 128 || bValid < 128) {
        uint4 z = make_uint4(0, 0, 0, 0);
        for (int i = tid; i < 2048; i += 256) {
            ((uint4*)sAhi)[i] = z; ((uint4*)sAlo)[i] = z;
            ((uint4*)sBhi)[i] = z; ((uint4*)sBlo)[i] = z;
        }
        __syncthreads();
    }

    // ---- fill A tile (hi/lo bf16 split, swizzled) ----
    for (int seg = tid; seg < aValid * 16; seg += 256) {
        int row = seg >> 4, cs = seg & 15;
        const float4* src = (const float4*)(A + (size_t)(rbase + row) * 128 + cs * 8);
        float4 x0 = src[0], x1 = src[1];
        float xs[8] = {x0.x, x0.y, x0.z, x0.w, x1.x, x1.y, x1.z, x1.w};
        uint32_t hp[4], lp[4];
        #pragma unroll
        for (int t = 0; t < 4; t++) {
            __nv_bfloat162 h2 = __float22bfloat162_rn(make_float2(xs[2*t], xs[2*t+1]));
            float2 hf = __bfloat1622float2(h2);
            __nv_bfloat162 l2 = __float22bfloat162_rn(make_float2(xs[2*t] - hf.x, xs[2*t+1] - hf.y));
            hp[t] = *(uint32_t*)&h2;
            lp[t] = *(uint32_t*)&l2;
        }
        uint32_t off = (uint32_t)(row * 256) + (((uint32_t)cs ^ ((uint32_t)row & 7u)) << 4);
        *(uint4*)(sAhi + off) = make_uint4(hp[0], hp[1], hp[2], hp[3]);
        *(uint4*)(sAlo + off) = make_uint4(lp[0], lp[1], lp[2], lp[3]);
    }
    // ---- fill B tile (row source selected by split) ----
    for (int seg = tid; seg < bValid * 16; seg += 256) {
        int row = seg >> 4, cs = seg & 15;
        int g   = cbase + row;
        const float* bsrc = (g < bsplit) ? (Bm + (size_t)g * 128)
                                         : (Bm2 + (size_t)(g - bsplit) * 128);
        const float4* src = (const float4*)(bsrc + cs * 8);
        float4 x0 = src[0], x1 = src[1];
        float xs[8] = {x0.x, x0.y, x0.z, x0.w, x1.x, x1.y, x1.z, x1.w};
        uint32_t hp[4], lp[4];
        #pragma unroll
        for (int t = 0; t < 4; t++) {
            __nv_bfloat162 h2 = __float22bfloat162_rn(make_float2(xs[2*t], xs[2*t+1]));
            float2 hf = __bfloat1622float2(h2);
            __nv_bfloat162 l2 = __float22bfloat162_rn(make_float2(xs[2*t] - hf.x, xs[2*t+1] - hf.y));
            hp[t] = *(uint32_t*)&h2;
            lp[t] = *(uint32_t*)&l2;
        }
        uint32_t off = (uint32_t)(row * 256) + (((uint32_t)cs ^ ((uint32_t)row & 7u)) << 4);
        *(uint4*)(sBhi + off) = make_uint4(hp[0], hp[1], hp[2], hp[3]);
        *(uint4*)(sBlo + off) = make_uint4(lp[0], lp[1], lp[2], lp[3]);
    }
    __syncthreads();

    // ---- warp tiling: 4(m) x 2(n), warp tile 32x64 ----
    const int wm = wid & 3;
    const int wn = wid >> 2;

    const int arow    = (lane & 7) + ((lane >> 3) & 1) * 8;
    const int achunk  = lane >> 4;
    const int brow    = (lane & 7) + ((lane >> 4) << 3);
    const int bchunk  = (lane >> 3) & 1;

    float c[2][8][4];
    #pragma unroll
    for (int mi = 0; mi < 2; mi++)
        #pragma unroll
        for (int j = 0; j < 8; j++)
            #pragma unroll
            for (int q = 0; q < 4; q++) c[mi][j][q] = 0.f;

    #pragma unroll
    for (int ks = 0; ks < 8; ks++) {
        uint32_t ah[2][4], al[2][4], bh[8][2], bl[8][2];
        #pragma unroll
        for (int mi = 0; mi < 2; mi++) {
            int r = wm * 32 + mi * 16 + arow;
            ldsm4(ah[mi], sw_addr(uAhi, r, ks * 2 + achunk));
            ldsm4(al[mi], sw_addr(uAlo, r, ks * 2 + achunk));
        }
        #pragma unroll
        for (int jj = 0; jj < 4; jj++) {
            int r = wn * 64 + jj * 16 + brow;
            uint32_t t[4];
            ldsm4(t, sw_addr(uBhi, r, ks * 2 + bchunk));
            bh[jj*2][0] = t[0]; bh[jj*2][1] = t[1];
            bh[jj*2+1][0] = t[2]; bh[jj*2+1][1] = t[3];
            ldsm4(t, sw_addr(uBlo, r, ks * 2 + bchunk));
            bl[jj*2][0] = t[0]; bl[jj*2][1] = t[1];
            bl[jj*2+1][0] = t[2]; bl[jj*2+1][1] = t[3];
        }
        #pragma unroll
        for (int mi = 0; mi < 2; mi++)
            #pragma unroll
            for (int j = 0; j < 8; j++) {
                mma_bf16(c[mi][j], ah[mi], bh[j]);
                mma_bf16(c[mi][j], al[mi], bh[j]);
                mma_bf16(c[mi][j], ah[mi], bl[j]);
            }
    }

    // ---- epilogue ----
    #pragma unroll
    for (int mi = 0; mi < 2; mi++) {
        int m0 = rbase + wm * 32 + mi * 16 + (lane >> 2);
        #pragma unroll
        for (int j = 0; j < 8; j++) {
            int ncol = wn * 64 + j * 8 + (lane & 3) * 2;
            int n = cbase + ncol;
            if (n < Ncols) {
                float b0 = sbias[ncol], b1 = sbias[ncol + 1];
                if (pack_mode == 0) {
                    if (m0 < M)
                        *(float2*)&Cmat[(size_t)m0 * ldC + n] =
                            make_float2(c[mi][j][0] + b0, c[mi][j][1] + b1);
                    if (m0 + 8 < M)
                        *(float2*)&Cmat[(size_t)(m0 + 8) * ldC + n] =
                            make_float2(c[mi][j][2] + b0, c[mi][j][3] + b1);
                } else {
                    size_t half = (n < G3) ? 0 : GXOFF;
                    int    cc   = (n < G3) ? n : n - G3;
                    if (m0 < M)
                        *(float2*)&Cmat[half + (size_t)m0 * G3 + cc] =
                            make_float2(c[mi][j][0] + b0, c[mi][j][1] + b1);
                    if (m0 + 8 < M)
                        *(float2*)&Cmat[half + (size_t)(m0 + 8) * G3 + cc] =
                            make_float2(c[mi][j][2] + b0, c[mi][j][3] + b1);
                }
            }
        }
    }
}

// ---------------- tree encoder (with inline token-dtype detection) ----------------
__global__ void tree_kernel(const void* __restrict__ tokens) {
    const int tree = blockIdx.x;
    const int j    = threadIdx.x;

    __shared__ int stok[TT];
    __shared__ int s_is64;
    if (threadIdx.x == 0) {
        // int64 little-endian tokens < 2^31 => odd int32 words all zero
        const int* ti = (const int*)tokens;
        int allz = 1;
        #pragma unroll
        for (int k = 0; k < 32; k++)
            if (ti[2*k + 1] != 0) allz = 0;
        s_is64 = allz;
    }
    __syncthreads();
    if (threadIdx.x < TT) {
        size_t idx = (size_t)tree * TT + threadIdx.x;
        int t;
        if (s_is64) t = (int)((const long long*)tokens)[idx];
        else        t = ((const int*)tokens)[idx];
        stok[threadIdx.x] = t;
    }
    __syncthreads();

    const float* base = g_emb_proj + j;
    float h[TT];
    #pragma unroll
    for (int i = 0; i < TT; i++)
        h[i] = base[(unsigned)stok[i] << 7];

    #pragma unroll
    for (int i = TT - 1; i >= 1; i--)
        h[(i - 1) >> 1] += h[i];

    float m = h[0];
    #pragma unroll
    for (int i = 1; i < TT; i++) m = fmaxf(m, h[i]);

    g_tree_vec[(size_t)tree * CC + j] = m;
}

// ---------------- GRU recurrence: 128 blocks = (dir, batch), 320 threads ----------------
// Matvec threads (i<300) produce sh_gh only. Elementwise threads (i<100) own
// their (r,z,n) gx triple, loaded directly from L2 with 2-deep prefetch.
__global__ __launch_bounds__(320) void gru_kernel(const float* __restrict__ w_hh_f,
                                                  const float* __restrict__ b_hh_f,
                                                  const float* __restrict__ w_hh_b,
                                                  const float* __restrict__ b_hh_b) {
    const int blk = blockIdx.x;
    const int dir = blk >> 6;
    const int b   = blk & 63;
    const int i   = threadIdx.x;

    const float* w_hh = dir ? w_hh_b : w_hh_f;
    const float* b_hh = dir ? b_hh_b : b_hh_f;

    __shared__ __align__(16) float sh_h[104];
    __shared__ float sh_gh[G3];

    unsigned long long w2[50];
    float bias = 0.f;
    if (i < G3) {
        const double2* wr = (const double2*)(w_hh + (size_t)i * HH);
        #pragma unroll
        for (int q = 0; q < 25; q++) {
            double2 t = wr[q];
            w2[2*q]     = d2u(t.x);
            w2[2*q + 1] = d2u(t.y);
        }
        bias = b_hh[i];
    }
    if (i < 104) sh_h[i] = 0.f;

    const float* gbase = g_gx + (dir ? GXOFF : 0) + (size_t)b * SS * G3;

    float pool = -3.0e38f;

    // 2-deep gx prefetch (threads i<100 only): cur, nxt triples
    float cr = 0.f, cz = 0.f, cn = 0.f, nr = 0.f, nz = 0.f, nn = 0.f;
    if (i < HH) {
        int t0 = dir ? (SS - 1) : 0;
        int t1 = dir ? (SS - 2) : 1;
        const float* p0 = gbase + (size_t)t0 * G3;
        const float* p1 = gbase + (size_t)t1 * G3;
        cr = p0[i]; cz = p0[HH + i]; cn = p0[2*HH + i];
        nr = p1[i]; nz = p1[HH + i]; nn = p1[2*HH + i];
    }

    for (int step = 0; step < SS; step++) {
        __syncthreads();                     // sh_h from previous step visible
        float pr = 0.f, pz = 0.f, pn = 0.f;
        if (i < HH && step + 2 < SS) {       // issue prefetch LDGs first
            int t = dir ? (SS - 3 - step) : (step + 2);
            const float* p = gbase + (size_t)t * G3;
            pr = p[i]; pz = p[HH + i]; pn = p[2*HH + i];
        }
        if (i < G3) {
            // 4 independent FFMA2 chains (dep depth ~13)
            unsigned long long a0 = 0ull, a1 = 0ull, a2 = 0ull, a3 = 0ull;
            const double2* hp = (const double2*)sh_h;
            #pragma unroll
            for (int q = 0; q < 12; q++) {
                double2 h2a = hp[2*q], h2b = hp[2*q + 1];
                fma2(a0, w2[4*q],     d2u(h2a.x));
                fma2(a1, w2[4*q + 1], d2u(h2a.y));
                fma2(a2, w2[4*q + 2], d2u(h2b.x));
                fma2(a3, w2[4*q + 3], d2u(h2b.y));
            }
            {   // q = 24 tail (pairs 48,49)
                double2 h2a = hp[24];
                fma2(a0, w2[48], d2u(h2a.x));
                fma2(a1, w2[49], d2u(h2a.y));
            }
            float s01 = (f2lo(a0) + f2hi(a0)) + (f2lo(a1) + f2hi(a1));
            float s23 = (f2lo(a2) + f2hi(a2)) + (f2lo(a3) + f2hi(a3));
            sh_gh[i] = bias + (s01 + s23);
        }
        __syncthreads();                     // gh published; old sh_h reads done
        if (i < HH) {
            float r = fast_sigmoid(cr + sh_gh[i]);
            float z = fast_sigmoid(cz + sh_gh[HH + i]);
            float n = fast_tanh(cn + r * sh_gh[2*HH + i]);
            float hn = (1.f - z) * n + z * sh_h[i];
            sh_h[i] = hn;
            pool = fmaxf(pool, hn);
            cr = nr; cz = nz; cn = nn;
            nr = pr; nz = pz; nn = pn;
        }
    }
    if (i < HH) g_pool[b * (2 * HH) + dir * HH + i] = pool;
}

// ---------------- final FC ----------------
__global__ void fc_kernel(const float* __restrict__ fc_w,
                          const float* __restrict__ fc_b,
                          float* __restrict__ out) {
    const int bb = blockIdx.x;
    const int o  = threadIdx.x;
    if (o < OUTD) {
        const float* p = g_pool + bb * (2 * HH);
        const float* w = fc_w + (size_t)o * (2 * HH);
        float s = fc_b[o];
        #pragma unroll 8
        for (int k = 0; k < 2 * HH; k++) s += p[k] * w[k];
        out[bb * OUTD + o] = s;
    }
}

// ---------------- launch ----------------
extern "C" void kernel_launch(void* const* d_in, const int* in_sizes, int n_in,
                              void* d_out, int out_size) {
    const void*  tokens = d_in[0];
    const float* emb    = (const float*)d_in[4];
    const float* w_lin  = (const float*)d_in[5];
    const float* b_lin  = (const float*)d_in[6];
    const float* w_ih_f = (const float*)d_in[7];
    const float* w_hh_f = (const float*)d_in[8];
    const float* b_ih_f = (const float*)d_in[9];
    const float* b_hh_f = (const float*)d_in[10];
    const float* w_ih_b = (const float*)d_in[11];
    const float* w_hh_b = (const float*)d_in[12];
    const float* b_ih_b = (const float*)d_in[13];
    const float* b_hh_b = (const float*)d_in[14];
    const float* fc_w   = (const float*)d_in[15];
    const float* fc_b   = (const float*)d_in[16];
    float* out = (float*)d_out;

    float *p_emb_proj, *p_tree_vec, *p_gx;
    cudaGetSymbolAddress((void**)&p_emb_proj, g_emb_proj);
    cudaGetSymbolAddress((void**)&p_tree_vec, g_tree_vec);
    cudaGetSymbolAddress((void**)&p_gx,       g_gx);

    cudaFuncSetAttribute(mma_gemm_kernel,
                         cudaFuncAttributeMaxDynamicSharedMemorySize, MMA_SMEM_BYTES);

    // 1) emb_proj = emb @ w_lin.T + b_lin   (50000 x 128, K=128)  [tensor cores]
    {
        dim3 grid((VV + 127) / 128, 1);
        mma_gemm_kernel<<<grid, 256, MMA_SMEM_BYTES>>>(emb, w_lin, w_lin,
                                                       b_lin, 0, CC,
                                                       p_emb_proj, VV, CC, CC, 0);
    }

    // 2) tree encode (inline dtype detect) -> tree_vec [12800,128]
    tree_kernel<<<NTREE, 128>>>(tokens);

    // 3) fused GRU input gates, packed [dir][b][t][300]  [tensor cores]
    //    B rows 0..299 from w_ih_f, 300..599 from w_ih_b (no pack kernel).
    {
        dim3 grid(NTREE / 128, (2 * G3 + 127) / 128);
        mma_gemm_kernel<<<grid, 256, MMA_SMEM_BYTES>>>(p_tree_vec, w_ih_f, w_ih_b,
                                                       b_ih_f, b_ih_b, G3,
                                                       p_gx, NTREE, 2 * G3, 2 * G3, 1);
    }

    // 4) GRU recurrence + max-over-time pool   [profiled launch: global idx 5]
    gru_kernel<<<2 * BB, 320>>>(w_hh_f, b_hh_f, w_hh_b, b_hh_b);

    // 5) final FC
    fc_kernel<<<BB, 128>>>(fc_w, fc_b, out);
}

// round 15
// speedup vs baseline: 1.0084x; 1.0084x over previous
#include <cuda_runtime.h>
#include <cuda_bf16.h>
#include <cstdint>

// ---------------- fixed problem dimensions ----------------
#define BB    64
#define SS    200
#define TT    32
#define VV    50000
#define EE    128
#define CC    128
#define HH    100
#define OUTD  104
#define NTREE (BB*SS)          // 12800
#define G3    (3*HH)           // 300
#define GXOFF ((size_t)NTREE*G3)   // offset of bwd half in packed gx

// ---------------- device scratch (static, no allocs) ----------------
__device__ float g_emb_proj[(size_t)VV*CC];     // 25.6 MB
__device__ float g_tree_vec[(size_t)NTREE*CC];  // 6.5 MB
__device__ float g_gx[(size_t)NTREE*(2*G3)];    // 30.7 MB packed: [dir][b][t][300]
__device__ float g_pool[BB*2*HH];

// ---------------- f32x2 helpers (GRU) ----------------
__device__ __forceinline__ void fma2(unsigned long long& d,
                                     unsigned long long a,
                                     unsigned long long b) {
    asm("fma.rn.f32x2 %0, %1, %2, %0;" : "+l"(d) : "l"(a), "l"(b));
}
__device__ __forceinline__ float f2lo(unsigned long long v) { return __uint_as_float((unsigned int)v); }
__device__ __forceinline__ float f2hi(unsigned long long v) { return __uint_as_float((unsigned int)(v >> 32)); }
__device__ __forceinline__ unsigned long long d2u(double x) { return (unsigned long long)__double_as_longlong(x); }

__device__ __forceinline__ float fast_sigmoid(float x) {
    return __fdividef(1.f, 1.f + __expf(-x));
}
__device__ __forceinline__ float fast_tanh(float x) {
    float t = __expf(-2.f * x);
    return __fdividef(1.f - t, 1.f + t);
}

// ---------------- warp-MMA helpers (plain PTX, no sm_103a-only features) ----------------
__device__ __forceinline__ uint32_t smem_u32(const void* p) {
    uint32_t a;
    asm("{ .reg .u64 t; cvta.to.shared.u64 t, %1; cvt.u32.u64 %0, t; }" : "=r"(a) : "l"(p));
    return a;
}
__device__ __forceinline__ void ldsm4(uint32_t* r, uint32_t addr) {
    asm volatile("ldmatrix.sync.aligned.m8n8.x4.shared.b16 {%0,%1,%2,%3}, [%4];"
                 : "=r"(r[0]), "=r"(r[1]), "=r"(r[2]), "=r"(r[3]) : "r"(addr));
}
__device__ __forceinline__ void mma_bf16(float* c, const uint32_t* a, const uint32_t* b) {
    asm volatile("mma.sync.aligned.m16n8k16.row.col.f32.bf16.bf16.f32 "
                 "{%0,%1,%2,%3}, {%4,%5,%6,%7}, {%8,%9}, {%0,%1,%2,%3};"
                 : "+f"(c[0]), "+f"(c[1]), "+f"(c[2]), "+f"(c[3])
                 : "r"(a[0]), "r"(a[1]), "r"(a[2]), "r"(a[3]), "r"(b[0]), "r"(b[1]));
}
__device__ __forceinline__ uint32_t sw_addr(uint32_t base, int row, int chunk) {
    return base + row * 256 + (((uint32_t)chunk ^ ((uint32_t)row & 7u)) << 4);
}

// ============================================================================
// Tensor-core GEMM via mma.sync (bf16, fp32 acc), split-precision:
//   C = Ah*Bh + Al*Bh + Ah*Bl + bias     (error ~2^-17 relative)
// B rows come from Bm (rows < bsplit) or Bm2 (rows >= bsplit); bias likewise.
// pack_mode==1: remap output (r, c<600) -> g_gx [dir][b][t][300] layout.
// ============================================================================
#define MMA_SMEM_BYTES (131072 + 256)

__global__ __launch_bounds__(256, 1)
void mma_gemm_kernel(const float* __restrict__ A,
                     const float* __restrict__ Bm,
                     const float* __restrict__ Bm2,
                     const float* __restrict__ bias,
                     const float* __restrict__ bias2,
                     int bsplit,
                     float* __restrict__ Cmat,
                     int M, int Ncols, int ldC, int pack_mode) {
    extern __shared__ char raw_smem[];
    uint32_t raw_u = smem_u32(raw_smem);
    uint32_t padb  = ((raw_u + 255u) & ~255u) - raw_u;
    char* sm = raw_smem + padb;
    const uint32_t uAhi = raw_u + padb;
    const uint32_t uAlo = uAhi + 32768;
    const uint32_t uBhi = uAhi + 65536;
    const uint32_t uBlo = uAhi + 98304;
    char* sAhi = sm;
    char* sAlo = sm + 32768;
    char* sBhi = sm + 65536;
    char* sBlo = sm + 98304;

    __shared__ float sbias[128];

    const int tid  = threadIdx.x;
    const int wid  = tid >> 5;
    const int lane = tid & 31;

    const int rbase  = blockIdx.x * 128;
    const int cbase  = blockIdx.y * 128;
    const int aValid = min(128, M - rbase);
    const int bValid = min(128, Ncols - cbase);

    if (tid < 128) {
        int g = cbase + tid;
        float bv = 0.f;
        if (g < Ncols)
            bv = (g < bsplit) ? (bias ? bias[g] : 0.f)
                              : (bias2 ? bias2[g - bsplit] : 0.f);
        sbias[tid] = bv;
    }

    if (aValid < 128 || bValid < 128) {
        uint4 z = make_uint4(0, 0, 0, 0);
        for (int i = tid; i < 2048; i += 256) {
            ((uint4*)sAhi)[i] = z; ((uint4*)sAlo)[i] = z;
            ((uint4*)sBhi)[i] = z; ((uint4*)sBlo)[i] = z;
        }
        __syncthreads();
    }

    // ---- fill A tile (hi/lo bf16 split, swizzled) ----
    for (int seg = tid; seg < aValid * 16; seg += 256) {
        int row = seg >> 4, cs = seg & 15;
        const float4* src = (const float4*)(A + (size_t)(rbase + row) * 128 + cs * 8);
        float4 x0 = src[0], x1 = src[1];
        float xs[8] = {x0.x, x0.y, x0.z, x0.w, x1.x, x1.y, x1.z, x1.w};
        uint32_t hp[4], lp[4];
        #pragma unroll
        for (int t = 0; t < 4; t++) {
            __nv_bfloat162 h2 = __float22bfloat162_rn(make_float2(xs[2*t], xs[2*t+1]));
            float2 hf = __bfloat1622float2(h2);
            __nv_bfloat162 l2 = __float22bfloat162_rn(make_float2(xs[2*t] - hf.x, xs[2*t+1] - hf.y));
            hp[t] = *(uint32_t*)&h2;
            lp[t] = *(uint32_t*)&l2;
        }
        uint32_t off = (uint32_t)(row * 256) + (((uint32_t)cs ^ ((uint32_t)row & 7u)) << 4);
        *(uint4*)(sAhi + off) = make_uint4(hp[0], hp[1], hp[2], hp[3]);
        *(uint4*)(sAlo + off) = make_uint4(lp[0], lp[1], lp[2], lp[3]);
    }
    // ---- fill B tile (row source selected by split) ----
    for (int seg = tid; seg < bValid * 16; seg += 256) {
        int row = seg >> 4, cs = seg & 15;
        int g   = cbase + row;
        const float* bsrc = (g < bsplit) ? (Bm + (size_t)g * 128)
                                         : (Bm2 + (size_t)(g - bsplit) * 128);
        const float4* src = (const float4*)(bsrc + cs * 8);
        float4 x0 = src[0], x1 = src[1];
        float xs[8] = {x0.x, x0.y, x0.z, x0.w, x1.x, x1.y, x1.z, x1.w};
        uint32_t hp[4], lp[4];
        #pragma unroll
        for (int t = 0; t < 4; t++) {
            __nv_bfloat162 h2 = __float22bfloat162_rn(make_float2(xs[2*t], xs[2*t+1]));
            float2 hf = __bfloat1622float2(h2);
            __nv_bfloat162 l2 = __float22bfloat162_rn(make_float2(xs[2*t] - hf.x, xs[2*t+1] - hf.y));
            hp[t] = *(uint32_t*)&h2;
            lp[t] = *(uint32_t*)&l2;
        }
        uint32_t off = (uint32_t)(row * 256) + (((uint32_t)cs ^ ((uint32_t)row & 7u)) << 4);
        *(uint4*)(sBhi + off) = make_uint4(hp[0], hp[1], hp[2], hp[3]);
        *(uint4*)(sBlo + off) = make_uint4(lp[0], lp[1], lp[2], lp[3]);
    }
    __syncthreads();

    // ---- warp tiling: 4(m) x 2(n), warp tile 32x64 ----
    const int wm = wid & 3;
    const int wn = wid >> 2;

    const int arow    = (lane & 7) + ((lane >> 3) & 1) * 8;
    const int achunk  = lane >> 4;
    const int brow    = (lane & 7) + ((lane >> 4) << 3);
    const int bchunk  = (lane >> 3) & 1;

    float c[2][8][4];
    #pragma unroll
    for (int mi = 0; mi < 2; mi++)
        #pragma unroll
        for (int j = 0; j < 8; j++)
            #pragma unroll
            for (int q = 0; q < 4; q++) c[mi][j][q] = 0.f;

    #pragma unroll
    for (int ks = 0; ks < 8; ks++) {
        uint32_t ah[2][4], al[2][4], bh[8][2], bl[8][2];
        #pragma unroll
        for (int mi = 0; mi < 2; mi++) {
            int r = wm * 32 + mi * 16 + arow;
            ldsm4(ah[mi], sw_addr(uAhi, r, ks * 2 + achunk));
            ldsm4(al[mi], sw_addr(uAlo, r, ks * 2 + achunk));
        }
        #pragma unroll
        for (int jj = 0; jj < 4; jj++) {
            int r = wn * 64 + jj * 16 + brow;
            uint32_t t[4];
            ldsm4(t, sw_addr(uBhi, r, ks * 2 + bchunk));
            bh[jj*2][0] = t[0]; bh[jj*2][1] = t[1];
            bh[jj*2+1][0] = t[2]; bh[jj*2+1][1] = t[3];
            ldsm4(t, sw_addr(uBlo, r, ks * 2 + bchunk));
            bl[jj*2][0] = t[0]; bl[jj*2][1] = t[1];
            bl[jj*2+1][0] = t[2]; bl[jj*2+1][1] = t[3];
        }
        #pragma unroll
        for (int mi = 0; mi < 2; mi++)
            #pragma unroll
            for (int j = 0; j < 8; j++) {
                mma_bf16(c[mi][j], ah[mi], bh[j]);
                mma_bf16(c[mi][j], al[mi], bh[j]);
                mma_bf16(c[mi][j], ah[mi], bl[j]);
            }
    }

    // ---- epilogue ----
    #pragma unroll
    for (int mi = 0; mi < 2; mi++) {
        int m0 = rbase + wm * 32 + mi * 16 + (lane >> 2);
        #pragma unroll
        for (int j = 0; j < 8; j++) {
            int ncol = wn * 64 + j * 8 + (lane & 3) * 2;
            int n = cbase + ncol;
            if (n < Ncols) {
                float b0 = sbias[ncol], b1 = sbias[ncol + 1];
                if (pack_mode == 0) {
                    if (m0 < M)
                        *(float2*)&Cmat[(size_t)m0 * ldC + n] =
                            make_float2(c[mi][j][0] + b0, c[mi][j][1] + b1);
                    if (m0 + 8 < M)
                        *(float2*)&Cmat[(size_t)(m0 + 8) * ldC + n] =
                            make_float2(c[mi][j][2] + b0, c[mi][j][3] + b1);
                } else {
                    size_t half = (n < G3) ? 0 : GXOFF;
                    int    cc   = (n < G3) ? n : n - G3;
                    if (m0 < M)
                        *(float2*)&Cmat[half + (size_t)m0 * G3 + cc] =
                            make_float2(c[mi][j][0] + b0, c[mi][j][1] + b1);
                    if (m0 + 8 < M)
                        *(float2*)&Cmat[half + (size_t)(m0 + 8) * G3 + cc] =
                            make_float2(c[mi][j][2] + b0, c[mi][j][3] + b1);
                }
            }
        }
    }
}

// ---------------- tree encoder (with inline token-dtype detection) ----------------
__global__ void tree_kernel(const void* __restrict__ tokens) {
    const int tree = blockIdx.x;
    const int j    = threadIdx.x;

    __shared__ int stok[TT];
    __shared__ int s_is64;
    if (threadIdx.x == 0) {
        // int64 little-endian tokens < 2^31 => odd int32 words all zero
        const int* ti = (const int*)tokens;
        int allz = 1;
        #pragma unroll
        for (int k = 0; k < 32; k++)
            if (ti[2*k + 1] != 0) allz = 0;
        s_is64 = allz;
    }
    __syncthreads();
    if (threadIdx.x < TT) {
        size_t idx = (size_t)tree * TT + threadIdx.x;
        int t;
        if (s_is64) t = (int)((const long long*)tokens)[idx];
        else        t = ((const int*)tokens)[idx];
        stok[threadIdx.x] = t;
    }
    __syncthreads();

    const float* base = g_emb_proj + j;
    float h[TT];
    #pragma unroll
    for (int i = 0; i < TT; i++)
        h[i] = base[(unsigned)stok[i] << 7];

    #pragma unroll
    for (int i = TT - 1; i >= 1; i--)
        h[(i - 1) >> 1] += h[i];

    float m = h[0];
    #pragma unroll
    for (int i = 1; i < TT; i++) m = fmaxf(m, h[i]);

    g_tree_vec[(size_t)tree * CC + j] = m;
}

// ---------------- GRU recurrence: 128 blocks = (dir, batch), 320 threads ----------------
// Matvec threads (i<300) produce sh_gh only. Elementwise threads (i<100) own
// their (r,z,n) gx triple, loaded directly from L2 with 2-deep prefetch.
__global__ __launch_bounds__(320) void gru_kernel(const float* __restrict__ w_hh_f,
                                                  const float* __restrict__ b_hh_f,
                                                  const float* __restrict__ w_hh_b,
                                                  const float* __restrict__ b_hh_b) {
    const int blk = blockIdx.x;
    const int dir = blk >> 6;
    const int b   = blk & 63;
    const int i   = threadIdx.x;

    const float* w_hh = dir ? w_hh_b : w_hh_f;
    const float* b_hh = dir ? b_hh_b : b_hh_f;

    __shared__ __align__(16) float sh_h[104];
    __shared__ float sh_gh[G3];

    unsigned long long w2[50];
    float bias = 0.f;
    if (i < G3) {
        const double2* wr = (const double2*)(w_hh + (size_t)i * HH);
        #pragma unroll
        for (int q = 0; q < 25; q++) {
            double2 t = wr[q];
            w2[2*q]     = d2u(t.x);
            w2[2*q + 1] = d2u(t.y);
        }
        bias = b_hh[i];
    }
    if (i < 104) sh_h[i] = 0.f;

    const float* gbase = g_gx + (dir ? GXOFF : 0) + (size_t)b * SS * G3;

    float pool = -3.0e38f;

    // 2-deep gx prefetch (threads i<100 only): cur, nxt triples
    float cr = 0.f, cz = 0.f, cn = 0.f, nr = 0.f, nz = 0.f, nn = 0.f;
    if (i < HH) {
        int t0 = dir ? (SS - 1) : 0;
        int t1 = dir ? (SS - 2) : 1;
        const float* p0 = gbase + (size_t)t0 * G3;
        const float* p1 = gbase + (size_t)t1 * G3;
        cr = p0[i]; cz = p0[HH + i]; cn = p0[2*HH + i];
        nr = p1[i]; nz = p1[HH + i]; nn = p1[2*HH + i];
    }

    for (int step = 0; step < SS; step++) {
        __syncthreads();                     // sh_h from previous step visible
        float pr = 0.f, pz = 0.f, pn = 0.f;
        if (i < HH && step + 2 < SS) {       // issue prefetch LDGs first
            int t = dir ? (SS - 3 - step) : (step + 2);
            const float* p = gbase + (size_t)t * G3;
            pr = p[i]; pz = p[HH + i]; pn = p[2*HH + i];
        }
        if (i < G3) {
            // 4 independent FFMA2 chains (dep depth ~13)
            unsigned long long a0 = 0ull, a1 = 0ull, a2 = 0ull, a3 = 0ull;
            const double2* hp = (const double2*)sh_h;
            #pragma unroll
            for (int q = 0; q < 12; q++) {
                double2 h2a = hp[2*q], h2b = hp[2*q + 1];
                fma2(a0, w2[4*q],     d2u(h2a.x));
                fma2(a1, w2[4*q + 1], d2u(h2a.y));
                fma2(a2, w2[4*q + 2], d2u(h2b.x));
                fma2(a3, w2[4*q + 3], d2u(h2b.y));
            }
            {   // q = 24 tail (pairs 48,49)
                double2 h2a = hp[24];
                fma2(a0, w2[48], d2u(h2a.x));
                fma2(a1, w2[49], d2u(h2a.y));
            }
            float s01 = (f2lo(a0) + f2hi(a0)) + (f2lo(a1) + f2hi(a1));
            float s23 = (f2lo(a2) + f2hi(a2)) + (f2lo(a3) + f2hi(a3));
            sh_gh[i] = bias + (s01 + s23);
        }
        __syncthreads();                     // gh published; old sh_h reads done
        if (i < HH) {
            float r = fast_sigmoid(cr + sh_gh[i]);
            float z = fast_sigmoid(cz + sh_gh[HH + i]);
            float n = fast_tanh(cn + r * sh_gh[2*HH + i]);
            float hn = (1.f - z) * n + z * sh_h[i];
            sh_h[i] = hn;
            pool = fmaxf(pool, hn);
            cr = nr; cz = nz; cn = nn;
            nr = pr; nz = pz; nn = pn;
        }
    }
    if (i < HH) g_pool[b * (2 * HH) + dir * HH + i] = pool;
}

// ---------------- final FC ----------------
__global__ void fc_kernel(const float* __restrict__ fc_w,
                          const float* __restrict__ fc_b,
                          float* __restrict__ out) {
    const int bb = blockIdx.x;
    const int o  = threadIdx.x;
    if (o < OUTD) {
        const float* p = g_pool + bb * (2 * HH);
        const float* w = fc_w + (size_t)o * (2 * HH);
        float s = fc_b[o];
        #pragma unroll 8
        for (int k = 0; k < 2 * HH; k++) s += p[k] * w[k];
        out[bb * OUTD + o] = s;
    }
}

// ---------------- launch ----------------
extern "C" void kernel_launch(void* const* d_in, const int* in_sizes, int n_in,
                              void* d_out, int out_size) {
    const void*  tokens = d_in[0];
    const float* emb    = (const float*)d_in[4];
    const float* w_lin  = (const float*)d_in[5];
    const float* b_lin  = (const float*)d_in[6];
    const float* w_ih_f = (const float*)d_in[7];
    const float* w_hh_f = (const float*)d_in[8];
    const float* b_ih_f = (const float*)d_in[9];
    const float* b_hh_f = (const float*)d_in[10];
    const float* w_ih_b = (const float*)d_in[11];
    const float* w_hh_b = (const float*)d_in[12];
    const float* b_ih_b = (const float*)d_in[13];
    const float* b_hh_b = (const float*)d_in[14];
    const float* fc_w   = (const float*)d_in[15];
    const float* fc_b   = (const float*)d_in[16];
    float* out = (float*)d_out;

    float *p_emb_proj, *p_tree_vec, *p_gx;
    cudaGetSymbolAddress((void**)&p_emb_proj, g_emb_proj);
    cudaGetSymbolAddress((void**)&p_tree_vec, g_tree_vec);
    cudaGetSymbolAddress((void**)&p_gx,       g_gx);

    cudaFuncSetAttribute(mma_gemm_kernel,
                         cudaFuncAttributeMaxDynamicSharedMemorySize, MMA_SMEM_BYTES);

    // 1) emb_proj = emb @ w_lin.T + b_lin   (50000 x 128, K=128)  [tensor cores]
    {
        dim3 grid((VV + 127) / 128, 1);
        mma_gemm_kernel<<<grid, 256, MMA_SMEM_BYTES>>>(emb, w_lin, w_lin,
                                                       b_lin, 0, CC,
                                                       p_emb_proj, VV, CC, CC, 0);
    }

    // 2) tree encode (inline dtype detect) -> tree_vec [12800,128]
    tree_kernel<<<NTREE, 128>>>(tokens);

    // 3) fused GRU input gates, packed [dir][b][t][300]  [tensor cores]
    //    B rows 0..299 from w_ih_f, 300..599 from w_ih_b (no pack kernel).
    {
        dim3 grid(NTREE / 128, (2 * G3 + 127) / 128);
        mma_gemm_kernel<<<grid, 256, MMA_SMEM_BYTES>>>(p_tree_vec, w_ih_f, w_ih_b,
                                                       b_ih_f, b_ih_b, G3,
                                                       p_gx, NTREE, 2 * G3, 2 * G3, 1);
    }

    // 4) GRU recurrence + max-over-time pool   [profiled launch: global idx 5]
    gru_kernel<<<2 * BB, 320>>>(w_hh_f, b_hh_f, w_hh_b, b_hh_b);

    // 5) final FC
    fc_kernel<<<BB, 128>>>(fc_w, fc_b, out);
}